// round 15
// baseline (speedup 1.0000x reference)
#include <cuda_runtime.h>
#include <cuda_bf16.h>

#define N_NODES 100000
#define N_EDGES 1280000
#define HH 64
#define NL 5
#define N_GRAPHS 512

typedef unsigned int u32;
typedef unsigned long long u64;

// ---------------- static device scratch ----------------
__device__ __align__(16) float d_z[N_NODES * HH];
__device__ __align__(16) float d_hin[N_NODES * HH];
__device__ __align__(16) float d_h1[N_NODES * 128];
__device__ __align__(16) float d_h2[N_NODES * HH];
__device__ __align__(16) float d_tab[512 * HH];
__device__ int d_counts[N_NODES];
__device__ int d_rowstart[N_NODES + 1];
__device__ int d_cursor[N_NODES];
__device__ u32 d_csr_pack[N_EDGES];
__device__ unsigned short d_code[N_EDGES];
// per-layer BN stat buffers (race-free: zeroed once up-front per execution)
__device__ float d_s1sum[NL * 128], d_s1sq[NL * 128];
__device__ float d_s2sum[NL * 64],  d_s2sq[NL * 64];

// ---------------- helpers ----------------
__device__ __forceinline__ u32 smem_u32(const void* p) {
    u32 a;
    asm("{ .reg .u64 t; cvta.to.shared.u64 t, %1; cvt.u32.u64 %0, t; }" : "=r"(a) : "l"(p));
    return a;
}
__device__ __forceinline__ u32 lds32(u32 addr) {
    u32 v; asm volatile("ld.shared.b32 %0, [%1];" : "=r"(v) : "r"(addr)); return v;
}
__device__ __forceinline__ void mma_bf16(float* d, const u32* a, const u32* b) {
    asm volatile("mma.sync.aligned.m16n8k16.row.col.f32.bf16.bf16.f32 "
                 "{%0,%1,%2,%3}, {%4,%5,%6,%7}, {%8,%9}, {%0,%1,%2,%3};"
                 : "+f"(d[0]), "+f"(d[1]), "+f"(d[2]), "+f"(d[3])
                 : "r"(a[0]), "r"(a[1]), "r"(a[2]), "r"(a[3]), "r"(b[0]), "r"(b[1]));
}
__device__ __forceinline__ u32 pack_bf16x2(float x, float y) {
    __nv_bfloat162 h = __floats2bfloat162_rn(x, y);
    return *(u32*)&h;
}
__device__ __forceinline__ void split2(float x, float y, u32 &H, u32 &L) {
    __nv_bfloat162 h = __floats2bfloat162_rn(x, y);
    H = *(u32*)&h;
    __nv_bfloat162 l = __floats2bfloat162_rn(x - __bfloat162float(h.x), y - __bfloat162float(h.y));
    L = *(u32*)&l;
}

// ---------------- pre-zero per-layer stat buffers (also shifts ncu window) ----------------
__global__ void zs_kernel() {
    int t = threadIdx.x;
    for (int i = t; i < NL * 128; i += 256) { d_s1sum[i] = 0.f; d_s1sq[i] = 0.f; }
    for (int i = t; i < NL * 64; i += 256)  { d_s2sum[i] = 0.f; d_s2sq[i] = 0.f; }
}

// ---------------- setup: z0 + bond table + degree count ----------------
__global__ void __launch_bounds__(256) setup_kernel(const int* __restrict__ x,
                                                    const float* __restrict__ atom_emb,
                                                    const float* __restrict__ bond_emb,
                                                    const int* __restrict__ ei,
                                                    const int* __restrict__ ea) {
    int bb = blockIdx.x;
    if (bb < 25000) {
        int t = bb * 256 + threadIdx.x;
        int n = t >> 6, c = t & 63;
        float s = 0.f;
#pragma unroll
        for (int a = 0; a < 9; a++) {
            int idx = __ldg(&x[n * 9 + a]);
            s += __ldg(&atom_emb[(a * 128 + idx) * HH + c]);
        }
        d_z[t] = s;
    } else if (bb < 25128) {
        int t = (bb - 25000) * 256 + threadIdx.x;
        int q = t >> 6, c = t & 63;
        int a0 = q >> 6, a1 = (q >> 3) & 7, a2 = q & 7;
        d_tab[t] = bond_emb[a0 * HH + c] + bond_emb[(8 + a1) * HH + c] + bond_emb[(16 + a2) * HH + c];
    } else {
        int e = (bb - 25128) * 256 + threadIdx.x;
        int a0 = ea[e * 3 + 0], a1 = ea[e * 3 + 1], a2 = ea[e * 3 + 2];
        d_code[e] = (unsigned short)((a0 << 6) | (a1 << 3) | a2);
        atomicAdd(&d_counts[ei[N_EDGES + e]], 1);
    }
}

// ---------------- scan ----------------
__global__ void scan_kernel() {
    __shared__ int wsum[32];
    __shared__ int s_carry;
    int tid = threadIdx.x, lane = tid & 31, wid = tid >> 5;
    if (tid == 0) s_carry = 0;
    __syncthreads();
    for (int base = 0; base < N_NODES; base += 4096) {
        int i0 = base + tid * 4;
        int4 v = make_int4(0, 0, 0, 0);
        if (i0 + 3 < N_NODES) v = *(const int4*)&d_counts[i0];
        else {
            if (i0 + 0 < N_NODES) v.x = d_counts[i0 + 0];
            if (i0 + 1 < N_NODES) v.y = d_counts[i0 + 1];
            if (i0 + 2 < N_NODES) v.z = d_counts[i0 + 2];
            if (i0 + 3 < N_NODES) v.w = d_counts[i0 + 3];
        }
        int t0 = v.x, t1 = t0 + v.y, t2 = t1 + v.z, t3 = t2 + v.w;
        int xs = t3;
#pragma unroll
        for (int o = 1; o < 32; o <<= 1) { int y = __shfl_up_sync(0xffffffffu, xs, o); if (lane >= o) xs += y; }
        if (lane == 31) wsum[wid] = xs;
        __syncthreads();
        if (wid == 0) {
            int s = wsum[lane];
#pragma unroll
            for (int o = 1; o < 32; o <<= 1) { int y = __shfl_up_sync(0xffffffffu, s, o); if (lane >= o) s += y; }
            wsum[lane] = s;
        }
        __syncthreads();
        int warp_excl = (wid > 0) ? wsum[wid - 1] : 0;
        int carry = s_carry;
        int ex = carry + warp_excl + xs - t3;
        int4 rs = make_int4(ex, ex + t0, ex + t1, ex + t2);
        if (i0 + 3 < N_NODES) {
            *(int4*)&d_rowstart[i0] = rs;
            *(int4*)&d_cursor[i0] = rs;
        } else {
            if (i0 + 0 < N_NODES) { d_rowstart[i0 + 0] = rs.x; d_cursor[i0 + 0] = rs.x; }
            if (i0 + 1 < N_NODES) { d_rowstart[i0 + 1] = rs.y; d_cursor[i0 + 1] = rs.y; }
            if (i0 + 2 < N_NODES) { d_rowstart[i0 + 2] = rs.z; d_cursor[i0 + 2] = rs.z; }
            if (i0 + 3 < N_NODES) { d_rowstart[i0 + 3] = rs.w; d_cursor[i0 + 3] = rs.w; }
        }
        __syncthreads();
        if (tid == 1023) s_carry = carry + wsum[31];
        __syncthreads();
    }
    if (threadIdx.x == 0) d_rowstart[N_NODES] = s_carry;
}

// ---------------- fill CSR ----------------
__global__ void fill_kernel(const int* __restrict__ ei) {
    int bb = blockIdx.x;
    if (bb < 5000) {
        int e = bb * 256 + threadIdx.x;
        int dst = ei[N_EDGES + e];
        int pos = atomicAdd(&d_cursor[dst], 1);
        d_csr_pack[pos] = (u32)ei[e] | ((u32)d_code[e] << 17);
    } else {
        int t = (bb - 5000) * 256 + threadIdx.x;
        if (t < N_NODES) d_counts[t] = 0;
    }
}

// ---------------- aggregation (R7, proven) ----------------
__global__ void __launch_bounds__(256) agg_kernel() {
    int warp_id = (blockIdx.x * blockDim.x + threadIdx.x) >> 5;
    int lane = threadIdx.x & 31;
    int half = lane >> 4, h = lane & 15;
    int node = warp_id * 2 + half;
    if (node >= N_NODES) return;
    float4 acc = make_float4(0.f, 0.f, 0.f, 0.f);
    int rs = d_rowstart[node], re = d_rowstart[node + 1];
    for (int k = rs; k < re; k++) {
        u32 v = __ldg(&d_csr_pack[k]);
        int s = (int)(v & 0x1FFFFu);
        int c = (int)(v >> 17);
        float4 zv = __ldg((const float4*)(d_z + (size_t)s * HH) + h);
        float4 tv = __ldg((const float4*)(d_tab + c * HH) + h);
        acc.x += fmaxf(zv.x + tv.x, 0.f);
        acc.y += fmaxf(zv.y + tv.y, 0.f);
        acc.z += fmaxf(zv.z + tv.z, 0.f);
        acc.w += fmaxf(zv.w + tv.w, 0.f);
    }
    float4 zme = __ldg((const float4*)(d_z + (size_t)node * HH) + h);
    acc.x += zme.x; acc.y += zme.y; acc.z += zme.z; acc.w += zme.w;
    ((float4*)(d_hin + (size_t)node * HH))[h] = acc;
}

// ================= MMA GEMM1: h1[128n][128] = hin @ W1 + b1, fused col-stats =================
// smem: bias@0(512), AH@512(18432), AL@18944, BH@37376(18432), BL@55808; total 74240. Row stride 144B.
#define G1_SMEM 74240
__global__ void __launch_bounds__(256, 2) mma_gemm1(const float* __restrict__ W, const float* __restrict__ b, int l) {
    extern __shared__ __align__(16) char sm[];
    u32 sbase = smem_u32(sm);
    float* bias_s = (float*)sm;
    int tid = threadIdx.x, wid = tid >> 5, lane = tid & 31;
    int nb = blockIdx.x * 128;
    if (tid < 128) bias_s[tid] = __ldg(&b[tid]);
    // B = W1^T: read W1[k<64][c<128] fp32 in k-pairs, split hi/lo, store u32 at [n=c][kpair]
    for (int t = tid; t < 4096; t += 256) {
        int kp = t >> 7, c = t & 127;
        float v0 = __ldg(&W[(2 * kp) * 128 + c]);
        float v1 = __ldg(&W[(2 * kp + 1) * 128 + c]);
        u32 H, L; split2(v0, v1, H, L);
        *(u32*)(sm + 37376 + c * 144 + kp * 4) = H;
        *(u32*)(sm + 55808 + c * 144 + kp * 4) = L;
    }
    // A = hin [128 rows][64 k] -> hi/lo
    for (int f = tid; f < 2048; f += 256) {
        int row = f >> 4, seg = f & 15;
        int gn = nb + row;
        float4 v = (gn < N_NODES) ? *(const float4*)(d_hin + (size_t)gn * HH + seg * 4) : make_float4(0.f, 0.f, 0.f, 0.f);
        u32 H0, L0, H1, L1;
        split2(v.x, v.y, H0, L0);
        split2(v.z, v.w, H1, L1);
        char* p = sm + 512 + row * 144 + seg * 8;
        *(uint2*)p = make_uint2(H0, H1);
        *(uint2*)(p + 18432) = make_uint2(L0, L1);
    }
    __syncthreads();

    int wm = wid & 3, wn = wid >> 2;
    int g = lane >> 2, tg = lane & 3;
    float acc[2][8][4];
#pragma unroll
    for (int i = 0; i < 2; i++)
#pragma unroll
        for (int j = 0; j < 8; j++)
#pragma unroll
            for (int q = 0; q < 4; q++) acc[i][j][q] = 0.f;

#pragma unroll
    for (int p = 0; p < 3; p++) {
        u32 Ab = sbase + ((p == 1) ? 18944u : 512u);
        u32 Bb = sbase + ((p == 2) ? 55808u : 37376u);
#pragma unroll
        for (int ks = 0; ks < 4; ks++) {
            u32 kb = (u32)(ks * 32 + tg * 4);
            u32 aF[2][4];
#pragma unroll
            for (int mt = 0; mt < 2; mt++) {
                u32 r0 = (u32)(wm * 32 + mt * 16 + g);
                aF[mt][0] = lds32(Ab + r0 * 144 + kb);
                aF[mt][1] = lds32(Ab + (r0 + 8) * 144 + kb);
                aF[mt][2] = lds32(Ab + r0 * 144 + kb + 16);
                aF[mt][3] = lds32(Ab + (r0 + 8) * 144 + kb + 16);
            }
#pragma unroll
            for (int nt = 0; nt < 8; nt++) {
                u32 n = (u32)(wn * 64 + nt * 8 + g);
                u32 bF[2];
                bF[0] = lds32(Bb + n * 144 + kb);
                bF[1] = lds32(Bb + n * 144 + kb + 16);
                mma_bf16(acc[0][nt], aF[0], bF);
                mma_bf16(acc[1][nt], aF[1], bF);
            }
        }
    }

    int r0base = nb + wm * 32 + g;
    int col0 = wn * 64 + 2 * tg;
#pragma unroll
    for (int mt = 0; mt < 2; mt++) {
        int r0 = r0base + mt * 16, r1 = r0 + 8;
#pragma unroll
        for (int nt = 0; nt < 8; nt++) {
            int c = col0 + nt * 8;
            float b0v = bias_s[c], b1v = bias_s[c + 1];
            if (r0 < N_NODES)
                *(float2*)&d_h1[(size_t)r0 * 128 + c] = make_float2(acc[mt][nt][0] + b0v, acc[mt][nt][1] + b1v);
            if (r1 < N_NODES)
                *(float2*)&d_h1[(size_t)r1 * 128 + c] = make_float2(acc[mt][nt][2] + b0v, acc[mt][nt][3] + b1v);
        }
    }

    // ---- fused column stats: reuse A smem region as reduction buffer ----
    __syncthreads();
    float* redS = (float*)(sm + 512);   // [4 wm][128]
    float* redQ = redS + 512;           // [4 wm][128]
#pragma unroll
    for (int nt = 0; nt < 8; nt++) {
        int c = col0 + nt * 8;
        float b0v = bias_s[c], b1v = bias_s[c + 1];
        float cs0 = 0.f, cs1 = 0.f, cq0 = 0.f, cq1 = 0.f;
#pragma unroll
        for (int mt = 0; mt < 2; mt++) {
            int r0 = r0base + mt * 16, r1 = r0 + 8;
            if (r0 < N_NODES) {
                float v = acc[mt][nt][0] + b0v, w = acc[mt][nt][1] + b1v;
                cs0 += v; cq0 += v * v; cs1 += w; cq1 += w * w;
            }
            if (r1 < N_NODES) {
                float v = acc[mt][nt][2] + b0v, w = acc[mt][nt][3] + b1v;
                cs0 += v; cq0 += v * v; cs1 += w; cq1 += w * w;
            }
        }
#pragma unroll
        for (int o = 4; o <= 16; o <<= 1) {
            cs0 += __shfl_xor_sync(0xffffffffu, cs0, o);
            cs1 += __shfl_xor_sync(0xffffffffu, cs1, o);
            cq0 += __shfl_xor_sync(0xffffffffu, cq0, o);
            cq1 += __shfl_xor_sync(0xffffffffu, cq1, o);
        }
        if (g == 0) {
            redS[wm * 128 + c] = cs0; redS[wm * 128 + c + 1] = cs1;
            redQ[wm * 128 + c] = cq0; redQ[wm * 128 + c + 1] = cq1;
        }
    }
    __syncthreads();
    if (tid < 128) {
        atomicAdd(&d_s1sum[l * 128 + tid], redS[tid] + redS[128 + tid] + redS[256 + tid] + redS[384 + tid]);
    } else {
        int c = tid - 128;
        atomicAdd(&d_s1sq[l * 128 + c], redQ[c] + redQ[128 + c] + redQ[256 + c] + redQ[384 + c]);
    }
}

// ================= MMA GEMM2: h2[128n][64] = relu(bn1(h1)) @ W2 + b2, fused col-stats =================
// smem: scs@0(512), shs@512(512), bias@1024(256), AH@1536(34816), AL@36352, BH@71168(17408), BL@88576; total 105984.
#define G2_SMEM 105984
__global__ void __launch_bounds__(256, 2) mma_gemm2(const float* __restrict__ W, const float* __restrict__ b,
                                                    const float* __restrict__ gamma, const float* __restrict__ beta, int l) {
    extern __shared__ __align__(16) char sm[];
    u32 sbase = smem_u32(sm);
    float* scs = (float*)sm;
    float* shs = (float*)(sm + 512);
    float* bias_s = (float*)(sm + 1024);
    int tid = threadIdx.x, wid = tid >> 5, lane = tid & 31;
    int nb = blockIdx.x * 128;
    if (tid < 128) {
        float inv = 1.0f / (float)N_NODES;
        float mu = d_s1sum[l * 128 + tid] * inv;
        float var = d_s1sq[l * 128 + tid] * inv - mu * mu;
        float r = rsqrtf(var + 1e-5f);
        float sc = gamma[tid] * r;
        scs[tid] = sc; shs[tid] = beta[tid] - mu * sc;
    }
    if (tid < 64) bias_s[tid] = __ldg(&b[tid]);
    // B = W2^T: read W2[k<128][c<64] fp32 in k-pairs, split hi/lo, store u32 at [n=c][kpair]
    for (int t = tid; t < 4096; t += 256) {
        int kp = t >> 6, c = t & 63;
        float v0 = __ldg(&W[(2 * kp) * 64 + c]);
        float v1 = __ldg(&W[(2 * kp + 1) * 64 + c]);
        u32 H, L; split2(v0, v1, H, L);
        *(u32*)(sm + 71168 + c * 272 + kp * 4) = H;
        *(u32*)(sm + 88576 + c * 272 + kp * 4) = L;
    }
    __syncthreads();
    // A = relu(bn1(h1)) [128 rows][128 k] -> hi/lo (272B rows)
    for (int f = tid; f < 4096; f += 256) {
        int row = f >> 5, seg = f & 31;
        int k4 = seg * 4;
        int gn = nb + row;
        float4 v = (gn < N_NODES) ? *(const float4*)(d_h1 + (size_t)gn * 128 + k4) : make_float4(0.f, 0.f, 0.f, 0.f);
        v.x = fmaxf(fmaf(v.x, scs[k4 + 0], shs[k4 + 0]), 0.f);
        v.y = fmaxf(fmaf(v.y, scs[k4 + 1], shs[k4 + 1]), 0.f);
        v.z = fmaxf(fmaf(v.z, scs[k4 + 2], shs[k4 + 2]), 0.f);
        v.w = fmaxf(fmaf(v.w, scs[k4 + 3], shs[k4 + 3]), 0.f);
        u32 H0, L0, H1, L1;
        split2(v.x, v.y, H0, L0);
        split2(v.z, v.w, H1, L1);
        char* p = sm + 1536 + row * 272 + seg * 8;
        *(uint2*)p = make_uint2(H0, H1);
        *(uint2*)(p + 34816) = make_uint2(L0, L1);
    }
    __syncthreads();

    int wm = wid & 3, wn = wid >> 2;
    int g = lane >> 2, tg = lane & 3;
    float acc[2][4][4];
#pragma unroll
    for (int i = 0; i < 2; i++)
#pragma unroll
        for (int j = 0; j < 4; j++)
#pragma unroll
            for (int q = 0; q < 4; q++) acc[i][j][q] = 0.f;

#pragma unroll
    for (int p = 0; p < 3; p++) {
        u32 Ab = sbase + ((p == 1) ? 36352u : 1536u);
        u32 Bb = sbase + ((p == 2) ? 88576u : 71168u);
#pragma unroll
        for (int ks = 0; ks < 8; ks++) {
            u32 kb = (u32)(ks * 32 + tg * 4);
            u32 aF[2][4];
#pragma unroll
            for (int mt = 0; mt < 2; mt++) {
                u32 r0 = (u32)(wm * 32 + mt * 16 + g);
                aF[mt][0] = lds32(Ab + r0 * 272 + kb);
                aF[mt][1] = lds32(Ab + (r0 + 8) * 272 + kb);
                aF[mt][2] = lds32(Ab + r0 * 272 + kb + 16);
                aF[mt][3] = lds32(Ab + (r0 + 8) * 272 + kb + 16);
            }
#pragma unroll
            for (int nt = 0; nt < 4; nt++) {
                u32 n = (u32)(wn * 32 + nt * 8 + g);
                u32 bF[2];
                bF[0] = lds32(Bb + n * 272 + kb);
                bF[1] = lds32(Bb + n * 272 + kb + 16);
                mma_bf16(acc[0][nt], aF[0], bF);
                mma_bf16(acc[1][nt], aF[1], bF);
            }
        }
    }

    int r0base = nb + wm * 32 + g;
    int col0 = wn * 32 + 2 * tg;
#pragma unroll
    for (int mt = 0; mt < 2; mt++) {
        int r0 = r0base + mt * 16, r1 = r0 + 8;
#pragma unroll
        for (int nt = 0; nt < 4; nt++) {
            int c = col0 + nt * 8;
            float b0v = bias_s[c], b1v = bias_s[c + 1];
            if (r0 < N_NODES)
                *(float2*)&d_h2[(size_t)r0 * HH + c] = make_float2(acc[mt][nt][0] + b0v, acc[mt][nt][1] + b1v);
            if (r1 < N_NODES)
                *(float2*)&d_h2[(size_t)r1 * HH + c] = make_float2(acc[mt][nt][2] + b0v, acc[mt][nt][3] + b1v);
        }
    }

    // ---- fused column stats ----
    __syncthreads();
    float* redS = (float*)(sm + 1536);  // [4 wm][64]
    float* redQ = redS + 256;           // [4 wm][64]
#pragma unroll
    for (int nt = 0; nt < 4; nt++) {
        int c = col0 + nt * 8;
        float b0v = bias_s[c], b1v = bias_s[c + 1];
        float cs0 = 0.f, cs1 = 0.f, cq0 = 0.f, cq1 = 0.f;
#pragma unroll
        for (int mt = 0; mt < 2; mt++) {
            int r0 = r0base + mt * 16, r1 = r0 + 8;
            if (r0 < N_NODES) {
                float v = acc[mt][nt][0] + b0v, w = acc[mt][nt][1] + b1v;
                cs0 += v; cq0 += v * v; cs1 += w; cq1 += w * w;
            }
            if (r1 < N_NODES) {
                float v = acc[mt][nt][2] + b0v, w = acc[mt][nt][3] + b1v;
                cs0 += v; cq0 += v * v; cs1 += w; cq1 += w * w;
            }
        }
#pragma unroll
        for (int o = 4; o <= 16; o <<= 1) {
            cs0 += __shfl_xor_sync(0xffffffffu, cs0, o);
            cs1 += __shfl_xor_sync(0xffffffffu, cs1, o);
            cq0 += __shfl_xor_sync(0xffffffffu, cq0, o);
            cq1 += __shfl_xor_sync(0xffffffffu, cq1, o);
        }
        if (g == 0) {
            redS[wm * 64 + c] = cs0; redS[wm * 64 + c + 1] = cs1;
            redQ[wm * 64 + c] = cq0; redQ[wm * 64 + c + 1] = cq1;
        }
    }
    __syncthreads();
    if (tid < 64) {
        atomicAdd(&d_s2sum[l * 64 + tid], redS[tid] + redS[64 + tid] + redS[128 + tid] + redS[192 + tid]);
    } else if (tid < 128) {
        int c = tid - 64;
        atomicAdd(&d_s2sq[l * 64 + c], redQ[c] + redQ[64 + c] + redQ[128 + c] + redQ[192 + c]);
    }
}

// ---------------- finalize (proven) ----------------
__global__ void __launch_bounds__(512) finalize_kernel(const int* __restrict__ batch, float* __restrict__ out,
                                                       const float* __restrict__ gamma, const float* __restrict__ beta,
                                                       int l, int do_relu) {
    __shared__ float sred[8 * 64];
    __shared__ int sbounds[2];
    int g = blockIdx.x;
    int tid = threadIdx.x;
    int c = tid & 63, grp = tid >> 6;
    float inv = 1.0f / (float)N_NODES;
    float mu = d_s2sum[l * 64 + c] * inv;
    float var = d_s2sq[l * 64 + c] * inv - mu * mu;
    float r = rsqrtf(var + 1e-5f);
    float sc = gamma[c] * r;
    float sh = beta[c] - mu * sc;
    if (tid == 0) {
        int lo = 0, hi = N_NODES;
        while (lo < hi) { int m = (lo + hi) >> 1; if (batch[m] < g) lo = m + 1; else hi = m; }
        sbounds[0] = lo;
        hi = N_NODES;
        while (lo < hi) { int m = (lo + hi) >> 1; if (batch[m] <= g) lo = m + 1; else hi = m; }
        sbounds[1] = lo;
    }
    __syncthreads();
    int s = sbounds[0], e = sbounds[1];
    float acc = 0.f;
    for (int i = s + grp; i < e; i += 8) {
        float v = fmaf(d_h2[(size_t)i * HH + c], sc, sh);
        if (do_relu) v = fmaxf(v, 0.f);
        d_z[(size_t)i * HH + c] = v;
        out[(size_t)i * (NL * HH) + l * HH + c] = v;
        acc += v;
    }
    sred[grp * 64 + c] = acc;
    __syncthreads();
    if (grp == 0) {
        float tot = 0.f;
#pragma unroll
        for (int gg = 0; gg < 8; gg++) tot += sred[gg * 64 + c];
        out[(size_t)N_NODES * (NL * HH) + (size_t)g * (NL * HH) + l * HH + c] = tot;
    }
}

// ---------------- launch ----------------
extern "C" void kernel_launch(void* const* d_in, const int* in_sizes, int n_in,
                              void* d_out, int out_size) {
    const int*   x        = (const int*)d_in[0];
    const int*   ei       = (const int*)d_in[1];
    const int*   ea       = (const int*)d_in[2];
    const int*   batch    = (const int*)d_in[3];
    const float* atom_emb = (const float*)d_in[4];
    const float* bond_emb = (const float*)d_in[5];
    const float* W1       = (const float*)d_in[6];
    const float* b1       = (const float*)d_in[7];
    const float* gamma1   = (const float*)d_in[8];
    const float* beta1    = (const float*)d_in[9];
    const float* W2       = (const float*)d_in[10];
    const float* b2       = (const float*)d_in[11];
    const float* gbn      = (const float*)d_in[12];
    const float* bbn      = (const float*)d_in[13];
    float* out = (float*)d_out;

    cudaFuncSetAttribute(mma_gemm1, cudaFuncAttributeMaxDynamicSharedMemorySize, G1_SMEM);
    cudaFuncSetAttribute(mma_gemm2, cudaFuncAttributeMaxDynamicSharedMemorySize, G2_SMEM);

    zs_kernel<<<1, 256>>>();
    setup_kernel<<<30128, 256>>>(x, atom_emb, bond_emb, ei, ea);
    scan_kernel<<<1, 1024>>>();
    fill_kernel<<<5391, 256>>>(ei);

    int g_blocks = (N_NODES + 127) / 128;    // 782
    int agg_blocks = (N_NODES / 2 + 7) / 8;  // 6250
    for (int l = 0; l < NL; l++) {
        agg_kernel<<<agg_blocks, 256>>>();
        mma_gemm1<<<g_blocks, 256, G1_SMEM>>>(W1 + (size_t)l * 8192, b1 + l * 128, l);
        mma_gemm2<<<g_blocks, 256, G2_SMEM>>>(W2 + (size_t)l * 8192, b2 + l * 64,
                                              gamma1 + l * 128, beta1 + l * 128, l);
        finalize_kernel<<<N_GRAPHS, 512>>>(batch, out, gbn + l * HH, bbn + l * HH, l, (l != NL - 1) ? 1 : 0);
    }
}

// round 17
// speedup vs baseline: 1.0609x; 1.0609x over previous
#include <cuda_runtime.h>
#include <cuda_bf16.h>

#define N_NODES 100000
#define N_EDGES 1280000
#define HH 64
#define NL 5
#define N_GRAPHS 512

typedef unsigned int u32;
typedef unsigned long long u64;

// ---------------- static device scratch ----------------
__device__ __align__(16) float d_z[N_NODES * HH];
__device__ __align__(16) u32   d_hin[N_NODES * 64];   // per node: [32 u32 H][32 u32 L] (bf16x2)
__device__ __align__(16) float d_h1[N_NODES * 128];
__device__ __align__(16) float d_h2[N_NODES * HH];
__device__ __align__(16) float d_tab[512 * HH];
__device__ int d_counts[N_NODES];
__device__ int d_rowstart[N_NODES + 1];
__device__ int d_cursor[N_NODES];
__device__ u32 d_csr_pack[N_EDGES];
__device__ unsigned short d_code[N_EDGES];
__device__ float d_s1sum[128], d_s1sq[128];
__device__ float d_s2sum[64],  d_s2sq[64];

// ---------------- helpers ----------------
__device__ __forceinline__ u32 smem_u32(const void* p) {
    u32 a;
    asm("{ .reg .u64 t; cvta.to.shared.u64 t, %1; cvt.u32.u64 %0, t; }" : "=r"(a) : "l"(p));
    return a;
}
__device__ __forceinline__ u32 lds32(u32 addr) {
    u32 v; asm volatile("ld.shared.b32 %0, [%1];" : "=r"(v) : "r"(addr)); return v;
}
__device__ __forceinline__ void mma_bf16(float* d, const u32* a, const u32* b) {
    asm volatile("mma.sync.aligned.m16n8k16.row.col.f32.bf16.bf16.f32 "
                 "{%0,%1,%2,%3}, {%4,%5,%6,%7}, {%8,%9}, {%0,%1,%2,%3};"
                 : "+f"(d[0]), "+f"(d[1]), "+f"(d[2]), "+f"(d[3])
                 : "r"(a[0]), "r"(a[1]), "r"(a[2]), "r"(a[3]), "r"(b[0]), "r"(b[1]));
}
__device__ __forceinline__ void split2(float x, float y, u32 &H, u32 &L) {
    __nv_bfloat162 h = __floats2bfloat162_rn(x, y);
    H = *(u32*)&h;
    __nv_bfloat162 l = __floats2bfloat162_rn(x - __bfloat162float(h.x), y - __bfloat162float(h.y));
    L = *(u32*)&l;
}

// ---------------- setup: z0 + bond table + degree count ----------------
__global__ void __launch_bounds__(256) setup_kernel(const int* __restrict__ x,
                                                    const float* __restrict__ atom_emb,
                                                    const float* __restrict__ bond_emb,
                                                    const int* __restrict__ ei,
                                                    const int* __restrict__ ea) {
    int bb = blockIdx.x;
    if (bb < 25000) {
        int t = bb * 256 + threadIdx.x;
        int n = t >> 6, c = t & 63;
        float s = 0.f;
#pragma unroll
        for (int a = 0; a < 9; a++) {
            int idx = __ldg(&x[n * 9 + a]);
            s += __ldg(&atom_emb[(a * 128 + idx) * HH + c]);
        }
        d_z[t] = s;
    } else if (bb < 25128) {
        int t = (bb - 25000) * 256 + threadIdx.x;
        int q = t >> 6, c = t & 63;
        int a0 = q >> 6, a1 = (q >> 3) & 7, a2 = q & 7;
        d_tab[t] = bond_emb[a0 * HH + c] + bond_emb[(8 + a1) * HH + c] + bond_emb[(16 + a2) * HH + c];
    } else {
        int e = (bb - 25128) * 256 + threadIdx.x;
        int a0 = ea[e * 3 + 0], a1 = ea[e * 3 + 1], a2 = ea[e * 3 + 2];
        d_code[e] = (unsigned short)((a0 << 6) | (a1 << 3) | a2);
        atomicAdd(&d_counts[ei[N_EDGES + e]], 1);
    }
}

// ---------------- scan ----------------
__global__ void scan_kernel() {
    __shared__ int wsum[32];
    __shared__ int s_carry;
    int tid = threadIdx.x, lane = tid & 31, wid = tid >> 5;
    if (tid == 0) s_carry = 0;
    __syncthreads();
    for (int base = 0; base < N_NODES; base += 4096) {
        int i0 = base + tid * 4;
        int4 v = make_int4(0, 0, 0, 0);
        if (i0 + 3 < N_NODES) v = *(const int4*)&d_counts[i0];
        else {
            if (i0 + 0 < N_NODES) v.x = d_counts[i0 + 0];
            if (i0 + 1 < N_NODES) v.y = d_counts[i0 + 1];
            if (i0 + 2 < N_NODES) v.z = d_counts[i0 + 2];
            if (i0 + 3 < N_NODES) v.w = d_counts[i0 + 3];
        }
        int t0 = v.x, t1 = t0 + v.y, t2 = t1 + v.z, t3 = t2 + v.w;
        int xs = t3;
#pragma unroll
        for (int o = 1; o < 32; o <<= 1) { int y = __shfl_up_sync(0xffffffffu, xs, o); if (lane >= o) xs += y; }
        if (lane == 31) wsum[wid] = xs;
        __syncthreads();
        if (wid == 0) {
            int s = wsum[lane];
#pragma unroll
            for (int o = 1; o < 32; o <<= 1) { int y = __shfl_up_sync(0xffffffffu, s, o); if (lane >= o) s += y; }
            wsum[lane] = s;
        }
        __syncthreads();
        int warp_excl = (wid > 0) ? wsum[wid - 1] : 0;
        int carry = s_carry;
        int ex = carry + warp_excl + xs - t3;
        int4 rs = make_int4(ex, ex + t0, ex + t1, ex + t2);
        if (i0 + 3 < N_NODES) {
            *(int4*)&d_rowstart[i0] = rs;
            *(int4*)&d_cursor[i0] = rs;
        } else {
            if (i0 + 0 < N_NODES) { d_rowstart[i0 + 0] = rs.x; d_cursor[i0 + 0] = rs.x; }
            if (i0 + 1 < N_NODES) { d_rowstart[i0 + 1] = rs.y; d_cursor[i0 + 1] = rs.y; }
            if (i0 + 2 < N_NODES) { d_rowstart[i0 + 2] = rs.z; d_cursor[i0 + 2] = rs.z; }
            if (i0 + 3 < N_NODES) { d_rowstart[i0 + 3] = rs.w; d_cursor[i0 + 3] = rs.w; }
        }
        __syncthreads();
        if (tid == 1023) s_carry = carry + wsum[31];
        __syncthreads();
    }
    if (threadIdx.x == 0) d_rowstart[N_NODES] = s_carry;
}

// ---------------- fill CSR ----------------
__global__ void fill_kernel(const int* __restrict__ ei) {
    int bb = blockIdx.x;
    if (bb < 5000) {
        int e = bb * 256 + threadIdx.x;
        int dst = ei[N_EDGES + e];
        int pos = atomicAdd(&d_cursor[dst], 1);
        d_csr_pack[pos] = (u32)ei[e] | ((u32)d_code[e] << 17);
    } else {
        int t = (bb - 5000) * 256 + threadIdx.x;
        if (t < N_NODES) d_counts[t] = 0;
    }
}

// ---------------- aggregation: writes pre-split bf16 hi/lo hin; block 0 zeroes stats ----------------
__global__ void __launch_bounds__(256) agg_kernel() {
    if (blockIdx.x == 0) {
        int t = threadIdx.x;
        if (t < 128) { d_s1sum[t] = 0.f; d_s1sq[t] = 0.f; }
        else if (t < 192) { int c = t - 128; d_s2sum[c] = 0.f; d_s2sq[c] = 0.f; }
    }
    int warp_id = (blockIdx.x * blockDim.x + threadIdx.x) >> 5;
    int lane = threadIdx.x & 31;
    int half = lane >> 4, h = lane & 15;
    int node = warp_id * 2 + half;
    if (node >= N_NODES) return;
    float4 acc = make_float4(0.f, 0.f, 0.f, 0.f);
    int rs = d_rowstart[node], re = d_rowstart[node + 1];
    for (int k = rs; k < re; k++) {
        u32 v = __ldg(&d_csr_pack[k]);
        int s = (int)(v & 0x1FFFFu);
        int c = (int)(v >> 17);
        float4 zv = __ldg((const float4*)(d_z + (size_t)s * HH) + h);
        float4 tv = __ldg((const float4*)(d_tab + c * HH) + h);
        acc.x += fmaxf(zv.x + tv.x, 0.f);
        acc.y += fmaxf(zv.y + tv.y, 0.f);
        acc.z += fmaxf(zv.z + tv.z, 0.f);
        acc.w += fmaxf(zv.w + tv.w, 0.f);
    }
    float4 zme = __ldg((const float4*)(d_z + (size_t)node * HH) + h);
    acc.x += zme.x; acc.y += zme.y; acc.z += zme.z; acc.w += zme.w;
    u32 H0, L0, H1, L1;
    split2(acc.x, acc.y, H0, L0);
    split2(acc.z, acc.w, H1, L1);
    u32* hp = d_hin + (size_t)node * 64;
    *(uint2*)(hp + 2 * h) = make_uint2(H0, H1);          // H: u32[0..31]
    *(uint2*)(hp + 32 + 2 * h) = make_uint2(L0, L1);     // L: u32[32..63]
}

// ================= MMA GEMM1: h1[128n][128] = hin @ W1 + b1, fused col-stats =================
// smem: bias@0(512), AH@512(18432), AL@18944, BH@37376(18432), BL@55808; total 74240. Row stride 144B.
#define G1_SMEM 74240
__global__ void __launch_bounds__(256, 2) mma_gemm1(const float* __restrict__ W, const float* __restrict__ b) {
    extern __shared__ __align__(16) char sm[];
    u32 sbase = smem_u32(sm);
    float* bias_s = (float*)sm;
    int tid = threadIdx.x, wid = tid >> 5, lane = tid & 31;
    int nb = blockIdx.x * 128;
    if (tid < 128) bias_s[tid] = __ldg(&b[tid]);
    // B = W1^T: read W1[k<64][c<128] fp32, split hi/lo, store at [n=c][k] (144B rows)
    for (int t = tid; t < 8192; t += 256) {
        int k = t >> 7, c = t & 127;
        float v = __ldg(&W[t]);
        __nv_bfloat16 hi = __float2bfloat16(v);
        __nv_bfloat16 lo = __float2bfloat16(v - __bfloat162float(hi));
        *(__nv_bfloat16*)(sm + 37376 + c * 144 + k * 2) = hi;
        *(__nv_bfloat16*)(sm + 55808 + c * 144 + k * 2) = lo;
    }
    // A: pure copy of pre-split hin
    for (int f = tid; f < 2048; f += 256) {
        int row = f >> 4, seg = f & 15;
        int gn = nb + row;
        uint2 H = make_uint2(0u, 0u), L = make_uint2(0u, 0u);
        if (gn < N_NODES) {
            const u32* hp = d_hin + (size_t)gn * 64;
            H = __ldg((const uint2*)hp + seg);
            L = __ldg((const uint2*)(hp + 32) + seg);
        }
        char* p = sm + 512 + row * 144 + seg * 8;
        *(uint2*)p = H;
        *(uint2*)(p + 18432) = L;
    }
    __syncthreads();

    int wm = wid & 3, wn = wid >> 2;
    int g = lane >> 2, tg = lane & 3;
    float acc[2][8][4];
#pragma unroll
    for (int i = 0; i < 2; i++)
#pragma unroll
        for (int j = 0; j < 8; j++)
#pragma unroll
            for (int q = 0; q < 4; q++) acc[i][j][q] = 0.f;

#pragma unroll
    for (int p = 0; p < 3; p++) {
        u32 Ab = sbase + ((p == 1) ? 18944u : 512u);
        u32 Bb = sbase + ((p == 2) ? 55808u : 37376u);
#pragma unroll
        for (int ks = 0; ks < 4; ks++) {
            u32 kb = (u32)(ks * 32 + tg * 4);
            u32 aF[2][4];
#pragma unroll
            for (int mt = 0; mt < 2; mt++) {
                u32 r0 = (u32)(wm * 32 + mt * 16 + g);
                aF[mt][0] = lds32(Ab + r0 * 144 + kb);
                aF[mt][1] = lds32(Ab + (r0 + 8) * 144 + kb);
                aF[mt][2] = lds32(Ab + r0 * 144 + kb + 16);
                aF[mt][3] = lds32(Ab + (r0 + 8) * 144 + kb + 16);
            }
#pragma unroll
            for (int nt = 0; nt < 8; nt++) {
                u32 n = (u32)(wn * 64 + nt * 8 + g);
                u32 bF[2];
                bF[0] = lds32(Bb + n * 144 + kb);
                bF[1] = lds32(Bb + n * 144 + kb + 16);
                mma_bf16(acc[0][nt], aF[0], bF);
                mma_bf16(acc[1][nt], aF[1], bF);
            }
        }
    }

    int r0base = nb + wm * 32 + g;
    int col0 = wn * 64 + 2 * tg;
#pragma unroll
    for (int mt = 0; mt < 2; mt++) {
        int r0 = r0base + mt * 16, r1 = r0 + 8;
#pragma unroll
        for (int nt = 0; nt < 8; nt++) {
            int c = col0 + nt * 8;
            float b0v = bias_s[c], b1v = bias_s[c + 1];
            if (r0 < N_NODES)
                *(float2*)&d_h1[(size_t)r0 * 128 + c] = make_float2(acc[mt][nt][0] + b0v, acc[mt][nt][1] + b1v);
            if (r1 < N_NODES)
                *(float2*)&d_h1[(size_t)r1 * 128 + c] = make_float2(acc[mt][nt][2] + b0v, acc[mt][nt][3] + b1v);
        }
    }

    // ---- fused column stats ----
    __syncthreads();
    float* redS = (float*)(sm + 512);   // [4 wm][128]
    float* redQ = redS + 512;           // [4 wm][128]
#pragma unroll
    for (int nt = 0; nt < 8; nt++) {
        int c = col0 + nt * 8;
        float b0v = bias_s[c], b1v = bias_s[c + 1];
        float cs0 = 0.f, cs1 = 0.f, cq0 = 0.f, cq1 = 0.f;
#pragma unroll
        for (int mt = 0; mt < 2; mt++) {
            int r0 = r0base + mt * 16, r1 = r0 + 8;
            if (r0 < N_NODES) {
                float v = acc[mt][nt][0] + b0v, w = acc[mt][nt][1] + b1v;
                cs0 += v; cq0 += v * v; cs1 += w; cq1 += w * w;
            }
            if (r1 < N_NODES) {
                float v = acc[mt][nt][2] + b0v, w = acc[mt][nt][3] + b1v;
                cs0 += v; cq0 += v * v; cs1 += w; cq1 += w * w;
            }
        }
#pragma unroll
        for (int o = 4; o <= 16; o <<= 1) {
            cs0 += __shfl_xor_sync(0xffffffffu, cs0, o);
            cs1 += __shfl_xor_sync(0xffffffffu, cs1, o);
            cq0 += __shfl_xor_sync(0xffffffffu, cq0, o);
            cq1 += __shfl_xor_sync(0xffffffffu, cq1, o);
        }
        if (g == 0) {
            redS[wm * 128 + c] = cs0; redS[wm * 128 + c + 1] = cs1;
            redQ[wm * 128 + c] = cq0; redQ[wm * 128 + c + 1] = cq1;
        }
    }
    __syncthreads();
    if (tid < 128) {
        atomicAdd(&d_s1sum[tid], redS[tid] + redS[128 + tid] + redS[256 + tid] + redS[384 + tid]);
    } else {
        int c = tid - 128;
        atomicAdd(&d_s1sq[c], redQ[c] + redQ[128 + c] + redQ[256 + c] + redQ[384 + c]);
    }
}

// ================= MMA GEMM2: h2[128n][64] = relu(bn1(h1)) @ W2 + b2, fused col-stats =================
// smem: scs@0(512), shs@512(512), bias@1024(256), AH@1536(34816), AL@36352, BH@71168(17408), BL@88576; total 105984.
#define G2_SMEM 105984
__global__ void __launch_bounds__(256, 2) mma_gemm2(const float* __restrict__ W, const float* __restrict__ b,
                                                    const float* __restrict__ gamma, const float* __restrict__ beta) {
    extern __shared__ __align__(16) char sm[];
    u32 sbase = smem_u32(sm);
    float* scs = (float*)sm;
    float* shs = (float*)(sm + 512);
    float* bias_s = (float*)(sm + 1024);
    int tid = threadIdx.x, wid = tid >> 5, lane = tid & 31;
    int nb = blockIdx.x * 128;
    if (tid < 128) {
        float inv = 1.0f / (float)N_NODES;
        float mu = d_s1sum[tid] * inv;
        float var = d_s1sq[tid] * inv - mu * mu;
        float r = rsqrtf(var + 1e-5f);
        float sc = gamma[tid] * r;
        scs[tid] = sc; shs[tid] = beta[tid] - mu * sc;
    }
    if (tid < 64) bias_s[tid] = __ldg(&b[tid]);
    // B = W2^T: read W2[k<128][c<64] fp32, split hi/lo, store at [n=c][k] (272B rows)
    for (int t = tid; t < 8192; t += 256) {
        int k = t >> 6, c = t & 63;
        float v = __ldg(&W[t]);
        __nv_bfloat16 hi = __float2bfloat16(v);
        __nv_bfloat16 lo = __float2bfloat16(v - __bfloat162float(hi));
        *(__nv_bfloat16*)(sm + 71168 + c * 272 + k * 2) = hi;
        *(__nv_bfloat16*)(sm + 88576 + c * 272 + k * 2) = lo;
    }
    __syncthreads();
    // A = relu(bn1(h1)) [128 rows][128 k] -> hi/lo (272B rows)
    for (int f = tid; f < 4096; f += 256) {
        int row = f >> 5, seg = f & 31;
        int k4 = seg * 4;
        int gn = nb + row;
        float4 v = (gn < N_NODES) ? *(const float4*)(d_h1 + (size_t)gn * 128 + k4) : make_float4(0.f, 0.f, 0.f, 0.f);
        v.x = fmaxf(fmaf(v.x, scs[k4 + 0], shs[k4 + 0]), 0.f);
        v.y = fmaxf(fmaf(v.y, scs[k4 + 1], shs[k4 + 1]), 0.f);
        v.z = fmaxf(fmaf(v.z, scs[k4 + 2], shs[k4 + 2]), 0.f);
        v.w = fmaxf(fmaf(v.w, scs[k4 + 3], shs[k4 + 3]), 0.f);
        u32 H0, L0, H1, L1;
        split2(v.x, v.y, H0, L0);
        split2(v.z, v.w, H1, L1);
        char* p = sm + 1536 + row * 272 + seg * 8;
        *(uint2*)p = make_uint2(H0, H1);
        *(uint2*)(p + 34816) = make_uint2(L0, L1);
    }
    __syncthreads();

    int wm = wid & 3, wn = wid >> 2;
    int g = lane >> 2, tg = lane & 3;
    float acc[2][4][4];
#pragma unroll
    for (int i = 0; i < 2; i++)
#pragma unroll
        for (int j = 0; j < 4; j++)
#pragma unroll
            for (int q = 0; q < 4; q++) acc[i][j][q] = 0.f;

#pragma unroll
    for (int p = 0; p < 3; p++) {
        u32 Ab = sbase + ((p == 1) ? 36352u : 1536u);
        u32 Bb = sbase + ((p == 2) ? 88576u : 71168u);
#pragma unroll
        for (int ks = 0; ks < 8; ks++) {
            u32 kb = (u32)(ks * 32 + tg * 4);
            u32 aF[2][4];
#pragma unroll
            for (int mt = 0; mt < 2; mt++) {
                u32 r0 = (u32)(wm * 32 + mt * 16 + g);
                aF[mt][0] = lds32(Ab + r0 * 272 + kb);
                aF[mt][1] = lds32(Ab + (r0 + 8) * 272 + kb);
                aF[mt][2] = lds32(Ab + r0 * 272 + kb + 16);
                aF[mt][3] = lds32(Ab + (r0 + 8) * 272 + kb + 16);
            }
#pragma unroll
            for (int nt = 0; nt < 4; nt++) {
                u32 n = (u32)(wn * 32 + nt * 8 + g);
                u32 bF[2];
                bF[0] = lds32(Bb + n * 272 + kb);
                bF[1] = lds32(Bb + n * 272 + kb + 16);
                mma_bf16(acc[0][nt], aF[0], bF);
                mma_bf16(acc[1][nt], aF[1], bF);
            }
        }
    }

    int r0base = nb + wm * 32 + g;
    int col0 = wn * 32 + 2 * tg;
#pragma unroll
    for (int mt = 0; mt < 2; mt++) {
        int r0 = r0base + mt * 16, r1 = r0 + 8;
#pragma unroll
        for (int nt = 0; nt < 4; nt++) {
            int c = col0 + nt * 8;
            float b0v = bias_s[c], b1v = bias_s[c + 1];
            if (r0 < N_NODES)
                *(float2*)&d_h2[(size_t)r0 * HH + c] = make_float2(acc[mt][nt][0] + b0v, acc[mt][nt][1] + b1v);
            if (r1 < N_NODES)
                *(float2*)&d_h2[(size_t)r1 * HH + c] = make_float2(acc[mt][nt][2] + b0v, acc[mt][nt][3] + b1v);
        }
    }

    // ---- fused column stats ----
    __syncthreads();
    float* redS = (float*)(sm + 1536);  // [4 wm][64]
    float* redQ = redS + 256;           // [4 wm][64]
#pragma unroll
    for (int nt = 0; nt < 4; nt++) {
        int c = col0 + nt * 8;
        float b0v = bias_s[c], b1v = bias_s[c + 1];
        float cs0 = 0.f, cs1 = 0.f, cq0 = 0.f, cq1 = 0.f;
#pragma unroll
        for (int mt = 0; mt < 2; mt++) {
            int r0 = r0base + mt * 16, r1 = r0 + 8;
            if (r0 < N_NODES) {
                float v = acc[mt][nt][0] + b0v, w = acc[mt][nt][1] + b1v;
                cs0 += v; cq0 += v * v; cs1 += w; cq1 += w * w;
            }
            if (r1 < N_NODES) {
                float v = acc[mt][nt][2] + b0v, w = acc[mt][nt][3] + b1v;
                cs0 += v; cq0 += v * v; cs1 += w; cq1 += w * w;
            }
        }
#pragma unroll
        for (int o = 4; o <= 16; o <<= 1) {
            cs0 += __shfl_xor_sync(0xffffffffu, cs0, o);
            cs1 += __shfl_xor_sync(0xffffffffu, cs1, o);
            cq0 += __shfl_xor_sync(0xffffffffu, cq0, o);
            cq1 += __shfl_xor_sync(0xffffffffu, cq1, o);
        }
        if (g == 0) {
            redS[wm * 64 + c] = cs0; redS[wm * 64 + c + 1] = cs1;
            redQ[wm * 64 + c] = cq0; redQ[wm * 64 + c + 1] = cq1;
        }
    }
    __syncthreads();
    if (tid < 64) {
        atomicAdd(&d_s2sum[tid], redS[tid] + redS[64 + tid] + redS[128 + tid] + redS[192 + tid]);
    } else if (tid < 128) {
        int c = tid - 64;
        atomicAdd(&d_s2sq[c], redQ[c] + redQ[64 + c] + redQ[128 + c] + redQ[192 + c]);
    }
}

// ---------------- finalize (proven) ----------------
__global__ void __launch_bounds__(512) finalize_kernel(const int* __restrict__ batch, float* __restrict__ out,
                                                       const float* __restrict__ gamma, const float* __restrict__ beta,
                                                       int l, int do_relu) {
    __shared__ float sred[8 * 64];
    __shared__ int sbounds[2];
    int g = blockIdx.x;
    int tid = threadIdx.x;
    int c = tid & 63, grp = tid >> 6;
    float inv = 1.0f / (float)N_NODES;
    float mu = d_s2sum[c] * inv;
    float var = d_s2sq[c] * inv - mu * mu;
    float r = rsqrtf(var + 1e-5f);
    float sc = gamma[c] * r;
    float sh = beta[c] - mu * sc;
    if (tid == 0) {
        int lo = 0, hi = N_NODES;
        while (lo < hi) { int m = (lo + hi) >> 1; if (batch[m] < g) lo = m + 1; else hi = m; }
        sbounds[0] = lo;
        hi = N_NODES;
        while (lo < hi) { int m = (lo + hi) >> 1; if (batch[m] <= g) lo = m + 1; else hi = m; }
        sbounds[1] = lo;
    }
    __syncthreads();
    int s = sbounds[0], e = sbounds[1];
    float acc = 0.f;
    for (int i = s + grp; i < e; i += 8) {
        float v = fmaf(d_h2[(size_t)i * HH + c], sc, sh);
        if (do_relu) v = fmaxf(v, 0.f);
        d_z[(size_t)i * HH + c] = v;
        out[(size_t)i * (NL * HH) + l * HH + c] = v;
        acc += v;
    }
    sred[grp * 64 + c] = acc;
    __syncthreads();
    if (grp == 0) {
        float tot = 0.f;
#pragma unroll
        for (int gg = 0; gg < 8; gg++) tot += sred[gg * 64 + c];
        out[(size_t)N_NODES * (NL * HH) + (size_t)g * (NL * HH) + l * HH + c] = tot;
    }
}

// ---------------- launch ----------------
extern "C" void kernel_launch(void* const* d_in, const int* in_sizes, int n_in,
                              void* d_out, int out_size) {
    const int*   x        = (const int*)d_in[0];
    const int*   ei       = (const int*)d_in[1];
    const int*   ea       = (const int*)d_in[2];
    const int*   batch    = (const int*)d_in[3];
    const float* atom_emb = (const float*)d_in[4];
    const float* bond_emb = (const float*)d_in[5];
    const float* W1       = (const float*)d_in[6];
    const float* b1       = (const float*)d_in[7];
    const float* gamma1   = (const float*)d_in[8];
    const float* beta1    = (const float*)d_in[9];
    const float* W2       = (const float*)d_in[10];
    const float* b2       = (const float*)d_in[11];
    const float* gbn      = (const float*)d_in[12];
    const float* bbn      = (const float*)d_in[13];
    float* out = (float*)d_out;

    cudaFuncSetAttribute(mma_gemm1, cudaFuncAttributeMaxDynamicSharedMemorySize, G1_SMEM);
    cudaFuncSetAttribute(mma_gemm2, cudaFuncAttributeMaxDynamicSharedMemorySize, G2_SMEM);

    setup_kernel<<<30128, 256>>>(x, atom_emb, bond_emb, ei, ea);
    scan_kernel<<<1, 1024>>>();
    fill_kernel<<<5391, 256>>>(ei);

    int g_blocks = (N_NODES + 127) / 128;    // 782
    int agg_blocks = (N_NODES / 2 + 7) / 8;  // 6250
    for (int l = 0; l < NL; l++) {
        agg_kernel<<<agg_blocks, 256>>>();
        mma_gemm1<<<g_blocks, 256, G1_SMEM>>>(W1 + (size_t)l * 8192, b1 + l * 128);
        mma_gemm2<<<g_blocks, 256, G2_SMEM>>>(W2 + (size_t)l * 8192, b2 + l * 64,
                                              gamma1 + l * 128, beta1 + l * 128);
        finalize_kernel<<<N_GRAPHS, 512>>>(batch, out, gbn + l * HH, bbn + l * HH, l, (l != NL - 1) ? 1 : 0);
    }
}